// round 5
// baseline (speedup 1.0000x reference)
#include <cuda_runtime.h>
#include <cstdint>

// ---------------------------------------------------------------------------
// B=512, N=256, H=128
//   A2 = A[:,:,:256] + A[:,:,256:]
//   d_i = rsqrt(rowsum(A2)+1)
//   A_mix[i,j] = 0.8*d_i*d_j*A2[i,j]  (i!=j),   0.1 + 0.7*d_i^2*(A2[i,i]+1)  (i==j)
//   out = A_mix @ (A_mix @ emb[idx])
// Pipeline: detect | prep(A->A2,d) | mix(A2->Amix tf32, in place) |
//           emb_round(emb->tf32) | gemm r0 | gemm r1
// ---------------------------------------------------------------------------

#define Bsz 512
#define Nn  256
#define Hh  128
#define NNODE 50000

__device__ float g_A2   [(size_t)Bsz * Nn * Nn];   // A2, then A_mix in place
__device__ float g_d    [(size_t)Bsz * Nn];
__device__ float g_H1   [(size_t)Bsz * Nn * Hh];
__device__ float g_embr [(size_t)NNODE * Hh];      // tf32-rounded embeddings
__device__ int   g_idx64;

// ---------------------------------------------------------------------------
__global__ void detect_kernel(const unsigned long long* __restrict__ idx) {
    int is64 = 1;
    #pragma unroll
    for (int i = 0; i < 16; i++)
        if (idx[i] >> 32) is64 = 0;
    g_idx64 = is64;
}

// ---------------------------------------------------------------------------
__device__ __forceinline__ float to_tf32(float x) {
    uint32_t u;
    asm("cvt.rna.tf32.f32 %0, %1;" : "=r"(u) : "f"(x));
    return __uint_as_float(u);
}

// ---------------------------------------------------------------------------
// prep: A2 = Ain + Aout, d = rsqrt(rowsum+1). Warp per row.
// ---------------------------------------------------------------------------
__global__ __launch_bounds__(256)
void prep_kernel(const float* __restrict__ A) {
    const int lane = threadIdx.x & 31;
    const int wid  = threadIdx.x >> 5;
    const int i    = blockIdx.x * 8 + wid;
    const int b    = blockIdx.y;

    const float* row = A + ((size_t)(b * Nn + i)) * (2 * Nn);
    const int j1 = lane * 4;
    const int j2 = lane * 4 + 128;

    float4 a0 = *(const float4*)(row + j1);
    float4 a1 = *(const float4*)(row + j2);
    float4 b0 = *(const float4*)(row + Nn + j1);
    float4 b1 = *(const float4*)(row + Nn + j2);

    float4 v0 = make_float4(a0.x + b0.x, a0.y + b0.y, a0.z + b0.z, a0.w + b0.w);
    float4 v1 = make_float4(a1.x + b1.x, a1.y + b1.y, a1.z + b1.z, a1.w + b1.w);

    float* dst = g_A2 + ((size_t)(b * Nn + i)) * Nn;
    *(float4*)(dst + j1) = v0;
    *(float4*)(dst + j2) = v1;

    float s = v0.x + v0.y + v0.z + v0.w + v1.x + v1.y + v1.z + v1.w;
    #pragma unroll
    for (int o = 16; o; o >>= 1) s += __shfl_xor_sync(0xFFFFFFFFu, s, o);
    if (lane == 0) g_d[b * Nn + i] = rsqrtf(s + 1.0f);
}

// ---------------------------------------------------------------------------
// mix: A2 -> A_mix (tf32-rna), in place. Warp per row.
// ---------------------------------------------------------------------------
__global__ __launch_bounds__(256)
void mix_kernel() {
    __shared__ float sd[Nn];
    const int lane = threadIdx.x & 31;
    const int wid  = threadIdx.x >> 5;
    const int i    = blockIdx.x * 8 + wid;
    const int b    = blockIdx.y;

    sd[threadIdx.x] = g_d[b * Nn + threadIdx.x];
    __syncthreads();

    float* row = g_A2 + ((size_t)(b * Nn + i)) * Nn;
    const float di = sd[i];

    #pragma unroll
    for (int h = 0; h < 2; h++) {
        const int j0 = lane * 4 + h * 128;
        float4 v = *(const float4*)(row + j0);
        float o[4] = { v.x, v.y, v.z, v.w };
        #pragma unroll
        for (int e = 0; e < 4; e++) {
            int j = j0 + e;
            float t;
            if (j == i) t = 0.1f + 0.7f * di * di * (o[e] + 1.0f);
            else        t = 0.8f * di * sd[j] * o[e];
            o[e] = to_tf32(t);
        }
        *(float4*)(row + j0) = make_float4(o[0], o[1], o[2], o[3]);
    }
}

// ---------------------------------------------------------------------------
// emb_round: g_embr = tf32_rna(emb).
// ---------------------------------------------------------------------------
__global__ __launch_bounds__(256)
void emb_round_kernel(const float* __restrict__ emb) {
    size_t i = ((size_t)blockIdx.x * 256 + threadIdx.x) * 4;
    float4 v = *(const float4*)(emb + i);
    v.x = to_tf32(v.x); v.y = to_tf32(v.y);
    v.z = to_tf32(v.z); v.w = to_tf32(v.w);
    *(float4*)(g_embr + i) = v;
}

// ---------------------------------------------------------------------------
// MMA / cp.async helpers
// ---------------------------------------------------------------------------
__device__ __forceinline__ void mma_tf32(float* c, const uint32_t* a, const uint32_t* b) {
    asm volatile(
        "mma.sync.aligned.m16n8k8.row.col.f32.tf32.tf32.f32 "
        "{%0,%1,%2,%3}, {%4,%5,%6,%7}, {%8,%9}, {%0,%1,%2,%3};\n"
        : "+f"(c[0]), "+f"(c[1]), "+f"(c[2]), "+f"(c[3])
        : "r"(a[0]), "r"(a[1]), "r"(a[2]), "r"(a[3]),
          "r"(b[0]), "r"(b[1]));
}

__device__ __forceinline__ void cp_async16(uint32_t smem_addr, const void* gptr) {
    asm volatile("cp.async.cg.shared.global [%0], [%1], 16;\n"
                 :: "r"(smem_addr), "l"(gptr));
}
__device__ __forceinline__ void cp_commit() {
    asm volatile("cp.async.commit_group;\n");
}
template <int N>
__device__ __forceinline__ void cp_wait() {
    asm volatile("cp.async.wait_group %0;\n" :: "n"(N) : "memory");
}

// ---------------------------------------------------------------------------
// GEMM: C[256,128] = A_mix[256,256] @ B[256,128]  (pure cp.async, 3 stages)
// round 0: B = g_embr[idx], C -> g_H1 (tf32-rounded)
// round 1: B = g_H1,        C -> out
// grid (2, 512), block 256 (8 warps, warp tile 64x32).
// ---------------------------------------------------------------------------
#define SA_STRIDE 36
#define SB_STRIDE 136
#define A_BUF (128 * SA_STRIDE)   // 4608 floats
#define B_BUF (32  * SB_STRIDE)   // 4352 floats
#define STAGES 3
#define SMEM_FLOATS (STAGES * (A_BUF + B_BUF))

__global__ __launch_bounds__(256, 2)
void sgc_gemm(const void* __restrict__ idx_raw,
              float* __restrict__ out,
              int round) {
    extern __shared__ float smem[];

    const int b    = blockIdx.y;
    const int row0 = blockIdx.x * 128;
    const int tid  = threadIdx.x;
    const int lane = tid & 31;
    const int w    = tid >> 5;
    const int wm   = w & 1;
    const int wn   = w >> 1;
    const int gr   = lane >> 2;
    const int tc   = lane & 3;

    const int idx64 = g_idx64;

    float acc[4][4][4];
    #pragma unroll
    for (int mt = 0; mt < 4; mt++)
        #pragma unroll
        for (int nt = 0; nt < 4; nt++)
            #pragma unroll
            for (int e = 0; e < 4; e++) acc[mt][nt][e] = 0.0f;

    const float* __restrict__ Ab = g_A2 + (size_t)b * Nn * Nn;  // A_mix (tf32)

    const int ar  = tid >> 3;
    const int ac4 = tid & 7;
    const int br  = tid >> 5;
    const int bc4 = tid & 31;

    auto b_src = [&](int gk) -> const float* {
        if (round == 0) {
            int pos = b * Nn + gk;
            long long node;
            if (idx64) node = ((const long long*)idx_raw)[pos];
            else       node = ((const int*)idx_raw)[pos];
            if (node < 0) node = 0;
            if (node >= NNODE) node = NNODE - 1;
            return g_embr + (size_t)node * Hh;
        }
        return g_H1 + ((size_t)(b * Nn + gk)) * Hh;
    };

    auto issue_tile = [&](int kt) {
        const int s  = kt % STAGES;
        const int k0 = kt * 32;
        float* dA = smem + s * (A_BUF + B_BUF);
        float* dB = dA + A_BUF;
        uint32_t baseA = (uint32_t)__cvta_generic_to_shared(dA);
        uint32_t baseB = (uint32_t)__cvta_generic_to_shared(dB);
        #pragma unroll
        for (int it = 0; it < 4; it++) {
            int r = ar + it * 32;
            cp_async16(baseA + (r * SA_STRIDE + ac4 * 4) * 4,
                       Ab + (size_t)(row0 + r) * Nn + k0 + ac4 * 4);
        }
        #pragma unroll
        for (int it = 0; it < 4; it++) {
            int r = br + it * 8;
            cp_async16(baseB + (r * SB_STRIDE + bc4 * 4) * 4,
                       b_src(k0 + r) + bc4 * 4);
        }
        cp_commit();
    };

    auto compute = [&](int kt) {
        const int s = kt % STAGES;
        const float* bufA = smem + s * (A_BUF + B_BUF);
        const float* bufB = bufA + A_BUF;
        #pragma unroll
        for (int ks = 0; ks < 4; ++ks) {
            const int kk = ks * 8;
            uint32_t af[4][4], bf[4][2];
            #pragma unroll
            for (int mt = 0; mt < 4; mt++) {
                int rb = wm * 64 + mt * 16;
                af[mt][0] = __float_as_uint(bufA[(rb + gr)     * SA_STRIDE + kk + tc]);
                af[mt][1] = __float_as_uint(bufA[(rb + 8 + gr) * SA_STRIDE + kk + tc]);
                af[mt][2] = __float_as_uint(bufA[(rb + gr)     * SA_STRIDE + kk + tc + 4]);
                af[mt][3] = __float_as_uint(bufA[(rb + 8 + gr) * SA_STRIDE + kk + tc + 4]);
            }
            #pragma unroll
            for (int nt = 0; nt < 4; nt++) {
                int cb = wn * 32 + nt * 8;
                bf[nt][0] = __float_as_uint(bufB[(kk + tc)     * SB_STRIDE + cb + gr]);
                bf[nt][1] = __float_as_uint(bufB[(kk + tc + 4) * SB_STRIDE + cb + gr]);
            }
            #pragma unroll
            for (int mt = 0; mt < 4; mt++)
                #pragma unroll
                for (int nt = 0; nt < 4; nt++)
                    mma_tf32(acc[mt][nt], af[mt], bf[nt]);
        }
    };

    // prologue: 2 tiles in flight
    issue_tile(0);
    issue_tile(1);

    // Drain semantics: while new tiles are still being issued (kt <= 5), tile
    // kt is the second-newest group -> wait_group 1. Once issuing stops
    // (kt >= 6), tile kt can be the NEWEST group -> must wait_group 0.
    #pragma unroll
    for (int kt = 0; kt < 8; ++kt) {
        if (kt < 6) cp_wait<1>();
        else        cp_wait<0>();
        __syncthreads();
        compute(kt);
        __syncthreads();
        if (kt + 2 < 8) issue_tile(kt + 2);
    }

    // epilogue
    const bool r0 = (round == 0);
    float* __restrict__ dst = r0 ? (g_H1 + (size_t)b * Nn * Hh)
                                 : (out  + (size_t)b * Nn * Hh);
    #pragma unroll
    for (int mt = 0; mt < 4; mt++) {
        int r_lo = row0 + wm * 64 + mt * 16 + gr;
        #pragma unroll
        for (int nt = 0; nt < 4; nt++) {
            int col = wn * 32 + nt * 8 + tc * 2;
            float o0 = acc[mt][nt][0], o1 = acc[mt][nt][1];
            float o2 = acc[mt][nt][2], o3 = acc[mt][nt][3];
            if (r0) {  // round-0 output feeds round-1 B: round to tf32 now
                o0 = to_tf32(o0); o1 = to_tf32(o1);
                o2 = to_tf32(o2); o3 = to_tf32(o3);
            }
            *(float2*)(dst + (size_t)r_lo       * Hh + col) = make_float2(o0, o1);
            *(float2*)(dst + (size_t)(r_lo + 8) * Hh + col) = make_float2(o2, o3);
        }
    }
}

// ---------------------------------------------------------------------------
extern "C" void kernel_launch(void* const* d_in, const int* in_sizes, int n_in,
                              void* d_out, int out_size) {
    const void*  inputs = nullptr;
    const float* A      = nullptr;
    const float* emb    = nullptr;

    for (int i = 0; i < n_in; ++i) {
        if (in_sizes[i] == Bsz * Nn)               inputs = d_in[i];
        else if (in_sizes[i] == Bsz * Nn * 2 * Nn) A      = (const float*)d_in[i];
        else if (in_sizes[i] == NNODE * Hh)        emb    = (const float*)d_in[i];
    }
    if (!inputs) inputs = d_in[0];
    if (!A)      A      = (const float*)d_in[1];
    if (!emb)    emb    = (const float*)d_in[2];

    float* out = (float*)d_out;

    static bool attr_set = false;
    const int smem_bytes = SMEM_FLOATS * sizeof(float);
    if (!attr_set) {
        cudaFuncSetAttribute(sgc_gemm, cudaFuncAttributeMaxDynamicSharedMemorySize,
                             smem_bytes);
        attr_set = true;
    }

    detect_kernel<<<1, 1>>>((const unsigned long long*)inputs);
    prep_kernel<<<dim3(Nn / 8, Bsz), 256>>>(A);
    mix_kernel<<<dim3(Nn / 8, Bsz), 256>>>();
    emb_round_kernel<<<(NNODE * Hh) / 1024, 256>>>(emb);
    sgc_gemm<<<dim3(2, Bsz), 256, smem_bytes>>>(inputs, out, 0);
    sgc_gemm<<<dim3(2, Bsz), 256, smem_bytes>>>(inputs, out, 1);
}

// round 6
// speedup vs baseline: 1.0658x; 1.0658x over previous
#include <cuda_runtime.h>
#include <cstdint>

// ---------------------------------------------------------------------------
// B=512, N=256, H=128
//   A2 = A[:,:,:256] + A[:,:,256:],  d_i = rsqrt(rowsum(A2)+1)
//   A_mix = 0.8*D*A2*D + diag(c),    c_i = 0.1 + d_i^2*(0.7 - 0.1*A2_ii)
//   out = A_mix @ (A_mix @ emb[idx])
// Z-space recurrence (Z = D*X):
//   Z0 = D * emb[idx]
//   W0 = A2 @ Z0 ;  Z1  = 0.8*d^2*W0 + c .* Z0
//   W1 = A2 @ Z1 ;  out = 0.8*d*W1   + (c/d) .* Z1
// Launches: detect | prep(A->A2 tf32, d, c) | zscale(Z0) | gemm r0 | gemm r1
// ---------------------------------------------------------------------------

#define Bsz 512
#define Nn  256
#define Hh  128
#define NNODE 50000

__device__ float g_A2 [(size_t)Bsz * Nn * Nn];   // A2, tf32-rna
__device__ float g_d  [(size_t)Bsz * Nn];
__device__ float g_c  [(size_t)Bsz * Nn];
__device__ float g_Z0 [(size_t)Bsz * Nn * Hh];
__device__ float g_Z1 [(size_t)Bsz * Nn * Hh];
__device__ int   g_idx64;

// ---------------------------------------------------------------------------
__global__ void detect_kernel(const unsigned long long* __restrict__ idx) {
    int is64 = 1;
    #pragma unroll
    for (int i = 0; i < 16; i++)
        if (idx[i] >> 32) is64 = 0;
    g_idx64 = is64;
}

__device__ __forceinline__ float to_tf32(float x) {
    uint32_t u;
    asm("cvt.rna.tf32.f32 %0, %1;" : "=r"(u) : "f"(x));
    return __uint_as_float(u);
}

// ---------------------------------------------------------------------------
// prep: A2 = Ain + Aout (stored tf32-rna), d = rsqrt(rowsum+1),
//       c = 0.1 + d^2*(0.7 - 0.1*A2_ii). Warp per row. grid (32,512), block 256.
// ---------------------------------------------------------------------------
__global__ __launch_bounds__(256)
void prep_kernel(const float* __restrict__ A) {
    const int lane = threadIdx.x & 31;
    const int wid  = threadIdx.x >> 5;
    const int i    = blockIdx.x * 8 + wid;
    const int b    = blockIdx.y;

    const float* row = A + ((size_t)(b * Nn + i)) * (2 * Nn);
    const int j1 = lane * 4;
    const int j2 = lane * 4 + 128;

    float4 a0 = *(const float4*)(row + j1);
    float4 a1 = *(const float4*)(row + j2);
    float4 b0 = *(const float4*)(row + Nn + j1);
    float4 b1 = *(const float4*)(row + Nn + j2);

    float4 v0 = make_float4(a0.x + b0.x, a0.y + b0.y, a0.z + b0.z, a0.w + b0.w);
    float4 v1 = make_float4(a1.x + b1.x, a1.y + b1.y, a1.z + b1.z, a1.w + b1.w);

    // store tf32-rounded A2 (GEMM operand)
    float* dst = g_A2 + ((size_t)(b * Nn + i)) * Nn;
    *(float4*)(dst + j1) = make_float4(to_tf32(v0.x), to_tf32(v0.y),
                                       to_tf32(v0.z), to_tf32(v0.w));
    *(float4*)(dst + j2) = make_float4(to_tf32(v1.x), to_tf32(v1.y),
                                       to_tf32(v1.z), to_tf32(v1.w));

    // rowsum (unrounded)
    float s = v0.x + v0.y + v0.z + v0.w + v1.x + v1.y + v1.z + v1.w;

    // diagonal element A2[i][i] (unrounded): held by lane (i&127)>>2
    const int dl = (i & 127) >> 2;
    const int dc = i & 3;
    const float4 vh = (i >> 7) ? v1 : v0;
    float elem = (dc == 0) ? vh.x : (dc == 1) ? vh.y : (dc == 2) ? vh.z : vh.w;
    float aii = (lane == dl) ? elem : 0.0f;

    #pragma unroll
    for (int o = 16; o; o >>= 1) {
        s   += __shfl_xor_sync(0xFFFFFFFFu, s,   o);
        aii += __shfl_xor_sync(0xFFFFFFFFu, aii, o);
    }
    if (lane == 0) {
        float d = rsqrtf(s + 1.0f);
        g_d[b * Nn + i] = d;
        g_c[b * Nn + i] = 0.1f + d * d * (0.7f - 0.1f * aii);
    }
}

// ---------------------------------------------------------------------------
// zscale: Z0[b,k,:] = rna(d[b,k] * emb[idx[b,k],:]). Warp per row.
// grid (Bsz*Nn/8), block 256.
// ---------------------------------------------------------------------------
__global__ __launch_bounds__(256)
void zscale_kernel(const void* __restrict__ idx_raw,
                   const float* __restrict__ emb) {
    const int lane = threadIdx.x & 31;
    const int wid  = threadIdx.x >> 5;
    const int r    = blockIdx.x * 8 + wid;     // global (b*Nn + k)

    long long node;
    if (g_idx64) node = ((const long long*)idx_raw)[r];
    else         node = ((const int*)idx_raw)[r];
    if (node < 0) node = 0;
    if (node >= NNODE) node = NNODE - 1;

    const float d = g_d[r];
    float4 v = *(const float4*)(emb + (size_t)node * Hh + lane * 4);
    v.x = to_tf32(d * v.x); v.y = to_tf32(d * v.y);
    v.z = to_tf32(d * v.z); v.w = to_tf32(d * v.w);
    *(float4*)(g_Z0 + (size_t)r * Hh + lane * 4) = v;
}

// ---------------------------------------------------------------------------
// MMA / cp.async helpers
// ---------------------------------------------------------------------------
__device__ __forceinline__ void mma_tf32(float* c, const uint32_t* a, const uint32_t* b) {
    asm volatile(
        "mma.sync.aligned.m16n8k8.row.col.f32.tf32.tf32.f32 "
        "{%0,%1,%2,%3}, {%4,%5,%6,%7}, {%8,%9}, {%0,%1,%2,%3};\n"
        : "+f"(c[0]), "+f"(c[1]), "+f"(c[2]), "+f"(c[3])
        : "r"(a[0]), "r"(a[1]), "r"(a[2]), "r"(a[3]),
          "r"(b[0]), "r"(b[1]));
}

__device__ __forceinline__ void cp_async16(uint32_t smem_addr, const void* gptr) {
    asm volatile("cp.async.cg.shared.global [%0], [%1], 16;\n"
                 :: "r"(smem_addr), "l"(gptr));
}
__device__ __forceinline__ void cp_commit() {
    asm volatile("cp.async.commit_group;\n");
}
template <int N>
__device__ __forceinline__ void cp_wait() {
    asm volatile("cp.async.wait_group %0;\n" :: "n"(N) : "memory");
}

// ---------------------------------------------------------------------------
// GEMM: W[256,128] = A2[256,256] @ Z[256,128], epilogue applies Z-recurrence.
// round 0: Z = g_Z0, writes Z1 = rna(0.8*d^2*W + c*Z0)      -> g_Z1
// round 1: Z = g_Z1, writes out = 0.8*d*W + (c/d)*Z1        -> out
// grid (2,512), block 256 (8 warps, warp tile 64x32), 3-stage cp.async.
// ---------------------------------------------------------------------------
#define SA_STRIDE 36
#define SB_STRIDE 136
#define A_BUF (128 * SA_STRIDE)
#define B_BUF (32  * SB_STRIDE)
#define STAGES 3
#define SMEM_FLOATS (STAGES * (A_BUF + B_BUF))

__global__ __launch_bounds__(256, 2)
void sgc_gemm(const float* __restrict__ Zsrc,
              float* __restrict__ dst_base,
              int round) {
    extern __shared__ float smem[];

    const int b    = blockIdx.y;
    const int row0 = blockIdx.x * 128;
    const int tid  = threadIdx.x;
    const int lane = tid & 31;
    const int w    = tid >> 5;
    const int wm   = w & 1;
    const int wn   = w >> 1;
    const int gr   = lane >> 2;
    const int tc   = lane & 3;

    float acc[4][4][4];
    #pragma unroll
    for (int mt = 0; mt < 4; mt++)
        #pragma unroll
        for (int nt = 0; nt < 4; nt++)
            #pragma unroll
            for (int e = 0; e < 4; e++) acc[mt][nt][e] = 0.0f;

    const float* __restrict__ Ab = g_A2 + (size_t)b * Nn * Nn;
    const float* __restrict__ Zb = Zsrc + (size_t)b * Nn * Hh;

    const int ar  = tid >> 3;
    const int ac4 = tid & 7;
    const int br  = tid >> 5;
    const int bc4 = tid & 31;

    auto issue_tile = [&](int kt) {
        const int s  = kt % STAGES;
        const int k0 = kt * 32;
        float* dA = smem + s * (A_BUF + B_BUF);
        float* dB = dA + A_BUF;
        uint32_t baseA = (uint32_t)__cvta_generic_to_shared(dA);
        uint32_t baseB = (uint32_t)__cvta_generic_to_shared(dB);
        #pragma unroll
        for (int it = 0; it < 4; it++) {
            int r = ar + it * 32;
            cp_async16(baseA + (r * SA_STRIDE + ac4 * 4) * 4,
                       Ab + (size_t)(row0 + r) * Nn + k0 + ac4 * 4);
        }
        #pragma unroll
        for (int it = 0; it < 4; it++) {
            int r = br + it * 8;
            cp_async16(baseB + (r * SB_STRIDE + bc4 * 4) * 4,
                       Zb + (size_t)(k0 + r) * Hh + bc4 * 4);
        }
        cp_commit();
    };

    auto compute = [&](int kt) {
        const int s = kt % STAGES;
        const float* bufA = smem + s * (A_BUF + B_BUF);
        const float* bufB = bufA + A_BUF;
        #pragma unroll
        for (int ks = 0; ks < 4; ++ks) {
            const int kk = ks * 8;
            uint32_t af[4][4], bf[4][2];
            #pragma unroll
            for (int mt = 0; mt < 4; mt++) {
                int rb = wm * 64 + mt * 16;
                af[mt][0] = __float_as_uint(bufA[(rb + gr)     * SA_STRIDE + kk + tc]);
                af[mt][1] = __float_as_uint(bufA[(rb + 8 + gr) * SA_STRIDE + kk + tc]);
                af[mt][2] = __float_as_uint(bufA[(rb + gr)     * SA_STRIDE + kk + tc + 4]);
                af[mt][3] = __float_as_uint(bufA[(rb + 8 + gr) * SA_STRIDE + kk + tc + 4]);
            }
            #pragma unroll
            for (int nt = 0; nt < 4; nt++) {
                int cb = wn * 32 + nt * 8;
                bf[nt][0] = __float_as_uint(bufB[(kk + tc)     * SB_STRIDE + cb + gr]);
                bf[nt][1] = __float_as_uint(bufB[(kk + tc + 4) * SB_STRIDE + cb + gr]);
            }
            #pragma unroll
            for (int mt = 0; mt < 4; mt++)
                #pragma unroll
                for (int nt = 0; nt < 4; nt++)
                    mma_tf32(acc[mt][nt], af[mt], bf[nt]);
        }
    };

    issue_tile(0);
    issue_tile(1);

    // Drain: while issuing continues (kt<6), tile kt is second-newest -> wait 1;
    // afterwards tile kt may be the newest group -> wait 0.
    #pragma unroll
    for (int kt = 0; kt < 8; ++kt) {
        if (kt < 6) cp_wait<1>();
        else        cp_wait<0>();
        __syncthreads();
        compute(kt);
        __syncthreads();
        if (kt + 2 < 8) issue_tile(kt + 2);
    }

    // ---- epilogue: Z-space recurrence ----
    const bool r0 = (round == 0);
    float* __restrict__ dst = dst_base + (size_t)b * Nn * Hh;

    #pragma unroll
    for (int mt = 0; mt < 4; mt++) {
        const int r_lo = row0 + wm * 64 + mt * 16 + gr;
        #pragma unroll
        for (int rr = 0; rr < 2; rr++) {
            const int r = r_lo + rr * 8;
            const float d = g_d[b * Nn + r];
            const float c = g_c[b * Nn + r];
            float ws, zs;   // W scale, Z scale
            if (r0) { ws = 0.8f * d * d; zs = c; }
            else    { ws = 0.8f * d;     zs = c / d; }
            #pragma unroll
            for (int nt = 0; nt < 4; nt++) {
                const int col = wn * 32 + nt * 8 + tc * 2;
                float2 z = *(const float2*)(Zb + (size_t)r * Hh + col);
                float o0 = ws * acc[mt][nt][rr * 2 + 0] + zs * z.x;
                float o1 = ws * acc[mt][nt][rr * 2 + 1] + zs * z.y;
                if (r0) { o0 = to_tf32(o0); o1 = to_tf32(o1); }
                *(float2*)(dst + (size_t)r * Hh + col) = make_float2(o0, o1);
            }
        }
    }
}

// ---------------------------------------------------------------------------
extern "C" void kernel_launch(void* const* d_in, const int* in_sizes, int n_in,
                              void* d_out, int out_size) {
    const void*  inputs = nullptr;
    const float* A      = nullptr;
    const float* emb    = nullptr;

    for (int i = 0; i < n_in; ++i) {
        if (in_sizes[i] == Bsz * Nn)               inputs = d_in[i];
        else if (in_sizes[i] == Bsz * Nn * 2 * Nn) A      = (const float*)d_in[i];
        else if (in_sizes[i] == NNODE * Hh)        emb    = (const float*)d_in[i];
    }
    if (!inputs) inputs = d_in[0];
    if (!A)      A      = (const float*)d_in[1];
    if (!emb)    emb    = (const float*)d_in[2];

    float* out = (float*)d_out;

    static bool attr_set = false;
    const int smem_bytes = SMEM_FLOATS * sizeof(float);
    if (!attr_set) {
        cudaFuncSetAttribute(sgc_gemm, cudaFuncAttributeMaxDynamicSharedMemorySize,
                             smem_bytes);
        attr_set = true;
    }

    float* z0; cudaGetSymbolAddress((void**)&z0, g_Z0);
    float* z1; cudaGetSymbolAddress((void**)&z1, g_Z1);

    detect_kernel<<<1, 1>>>((const unsigned long long*)inputs);
    prep_kernel<<<dim3(Nn / 8, Bsz), 256>>>(A);
    zscale_kernel<<<(Bsz * Nn) / 8, 256>>>(inputs, emb);
    sgc_gemm<<<dim3(2, Bsz), 256, smem_bytes>>>(z0, z1,  0);
    sgc_gemm<<<dim3(2, Bsz), 256, smem_bytes>>>(z1, out, 1);
}

// round 7
// speedup vs baseline: 1.2191x; 1.1438x over previous
#include <cuda_runtime.h>
#include <cstdint>

// ---------------------------------------------------------------------------
// B=512, N=256, H=128
//   A2 = A[:,:,:256] + A[:,:,256:],  d_i = rsqrt(rowsum(A2)+1)
//   A_mix = 0.8*D*A2*D + diag(c),    c_i = 0.1 + d_i^2*(0.7 - 0.1*A2_ii)
//   out = A_mix @ (A_mix @ emb[idx])
// Z-space:  Z0 = D*emb[idx];  Z1 = 0.8 d^2 (A2@Z0) + c.*Z0;
//           out = 0.8 d (A2@Z1) + (c/d).*Z1
// Launches: detect | prep (A -> fragment-permuted tf32 A2, d, c) | fused gemm
//
// Fragment-permuted A2 layout (per batch): [mblk 16][ksg 32][lane 32][4]
//   element e of lane (gr=lane>>2, tc=lane&3):
//   A2[mblk*16 + gr + (e&1)*8][ksg*8 + tc + (e>>1)*4]
// so each lane's m16n8k8 A-fragment is ONE contiguous float4.
// ---------------------------------------------------------------------------

#define Bsz 512
#define Nn  256
#define Hh  128
#define NNODE 50000

__device__ float g_A2p[(size_t)Bsz * Nn * Nn];   // fragment-permuted, tf32-rna
__device__ float g_d  [(size_t)Bsz * Nn];
__device__ float g_c  [(size_t)Bsz * Nn];
__device__ int   g_idx64;

// ---------------------------------------------------------------------------
__global__ void detect_kernel(const unsigned long long* __restrict__ idx) {
    int is64 = 1;
    #pragma unroll
    for (int i = 0; i < 16; i++)
        if (idx[i] >> 32) is64 = 0;
    g_idx64 = is64;
}

__device__ __forceinline__ float to_tf32(float x) {
    uint32_t u;
    asm("cvt.rna.tf32.f32 %0, %1;" : "=r"(u) : "f"(x));
    return __uint_as_float(u);
}

// ---------------------------------------------------------------------------
// prep: block = (mblk 16-row slab, batch). Stage A2 slab in smem, compute
// rowsums/d/c, write fragment-permuted tf32 A2. All gmem accesses coalesced.
// grid (16, 512), block 256.
// ---------------------------------------------------------------------------
__global__ __launch_bounds__(256)
void prep_kernel(const float* __restrict__ A) {
    __shared__ float s2[16 * 260];   // stride 260: 4*gr+tc banks distinct
    const int b    = blockIdx.y;
    const int mblk = blockIdx.x;
    const int t    = threadIdx.x;
    const int i0   = mblk * 16;

    // load 16 rows x 256 cols, summing in/out halves
    #pragma unroll
    for (int p = 0; p < 4; p++) {
        int fidx = t + p * 256;          // 0..1023
        int row  = fidx >> 6;
        int c4   = fidx & 63;
        const float4* src =
            (const float4*)(A + ((size_t)(b * Nn + i0 + row)) * (2 * Nn));
        float4 a  = src[c4];
        float4 bb = src[c4 + 64];
        *(float4*)(s2 + row * 260 + c4 * 4) =
            make_float4(a.x + bb.x, a.y + bb.y, a.z + bb.z, a.w + bb.w);
    }
    __syncthreads();

    // rowsum + diag -> d, c (8 warps, 2 rows each)
    const int lane = t & 31, w = t >> 5;
    #pragma unroll
    for (int rr = 0; rr < 2; rr++) {
        int row = w * 2 + rr;
        float s = 0.0f;
        #pragma unroll
        for (int k = 0; k < 8; k++) s += s2[row * 260 + lane + 32 * k];
        #pragma unroll
        for (int o = 16; o; o >>= 1) s += __shfl_xor_sync(0xFFFFFFFFu, s, o);
        if (lane == 0) {
            int i = i0 + row;
            float aii = s2[row * 260 + i];
            float d = rsqrtf(s + 1.0f);
            g_d[b * Nn + i] = d;
            g_c[b * Nn + i] = 0.1f + d * d * (0.7f - 0.1f * aii);
        }
    }

    // fragment-permuted tf32 write (reads s2, fully coalesced float4 stores)
    float4* dst = (float4*)g_A2p + ((size_t)(b * 16 + mblk)) * 1024;
    #pragma unroll
    for (int p = 0; p < 4; p++) {
        int q   = t + p * 256;           // 0..1023 = ksg*32 + lane'
        int ksg = q >> 5;
        int lp  = q & 31;
        int gr2 = lp >> 2, tc2 = lp & 3;
        float e0 = s2[(gr2    ) * 260 + ksg * 8 + tc2    ];
        float e1 = s2[(gr2 + 8) * 260 + ksg * 8 + tc2    ];
        float e2 = s2[(gr2    ) * 260 + ksg * 8 + tc2 + 4];
        float e3 = s2[(gr2 + 8) * 260 + ksg * 8 + tc2 + 4];
        dst[q] = make_float4(to_tf32(e0), to_tf32(e1), to_tf32(e2), to_tf32(e3));
    }
}

// ---------------------------------------------------------------------------
// MMA / cp.async helpers
// ---------------------------------------------------------------------------
__device__ __forceinline__ void mma_tf32(float* c, const uint32_t* a, const uint32_t* b) {
    asm volatile(
        "mma.sync.aligned.m16n8k8.row.col.f32.tf32.tf32.f32 "
        "{%0,%1,%2,%3}, {%4,%5,%6,%7}, {%8,%9}, {%0,%1,%2,%3};\n"
        : "+f"(c[0]), "+f"(c[1]), "+f"(c[2]), "+f"(c[3])
        : "r"(a[0]), "r"(a[1]), "r"(a[2]), "r"(a[3]),
          "r"(b[0]), "r"(b[1]));
}

__device__ __forceinline__ void cp_async16(uint32_t smem_addr, const void* gptr) {
    asm volatile("cp.async.cg.shared.global [%0], [%1], 16;\n"
                 :: "r"(smem_addr), "l"(gptr));
}
__device__ __forceinline__ void cp_commit() {
    asm volatile("cp.async.commit_group;\n");
}
template <int N>
__device__ __forceinline__ void cp_wait() {
    asm volatile("cp.async.wait_group %0;\n" :: "n"(N) : "memory");
}

// ---------------------------------------------------------------------------
// Fused GEMM: one CTA per batch. 512 threads (16 warps, 4x4 warp grid,
// warp tile 64x32, CTA tile 256x128). Z resident in smem; A2 streamed via
// 2-stage cp.async (round 1 re-read hits L2). Both propagation rounds fused.
// ---------------------------------------------------------------------------
#define SZ_STRIDE 132          // 4*tc+gr banks distinct for B frag loads
#define A_STAGE   8192         // floats per A stage (256x32 permuted)
#define SMEM_FLOATS (Nn * SZ_STRIDE + 2 * A_STAGE + 2 * Nn)

__global__ __launch_bounds__(512, 1)
void sgc_fused(const void* __restrict__ idx_raw,
               const float* __restrict__ emb,
               float* __restrict__ out) {
    extern __shared__ float smem[];
    float* sZ = smem;                       // [256][132]
    float* sA = smem + Nn * SZ_STRIDE;      // 2 stages x 8192
    float* sd = sA + 2 * A_STAGE;           // [256]
    float* sc = sd + Nn;                    // [256]

    const int b    = blockIdx.x;
    const int tid  = threadIdx.x;
    const int lane = tid & 31;
    const int w    = tid >> 5;
    const int wm   = w & 3;     // m block (64 rows)
    const int wn   = w >> 2;    // n block (32 cols)
    const int gr   = lane >> 2;
    const int tc   = lane & 3;

    if (tid < 256) sd[tid] = g_d[b * Nn + tid];
    else           sc[tid - 256] = g_c[b * Nn + (tid - 256)];

    const float4* __restrict__ A2b = (const float4*)g_A2p + (size_t)b * 16384;

    auto issue_tile = [&](int kt, int s) {
        uint32_t base = (uint32_t)__cvta_generic_to_shared(sA + s * A_STAGE);
        #pragma unroll
        for (int p = 0; p < 4; p++) {
            int chunk = tid + p * 512;       // 0..2047
            int mb    = chunk >> 7;
            int rest  = chunk & 127;
            cp_async16(base + chunk * 16, A2b + mb * 1024 + kt * 128 + rest);
        }
        cp_commit();
    };

    // overlap: A tiles 0,1 in flight while Z0 is gathered
    issue_tile(0, 0);
    issue_tile(1, 1);
    __syncthreads();   // sd visible

    // Z0 = rna(d * emb[idx]) directly into smem (2 threads per row)
    {
        const int r    = tid >> 1;
        const int half = tid & 1;
        long long node;
        if (g_idx64) node = ((const long long*)idx_raw)[b * Nn + r];
        else         node = ((const int*)idx_raw)[b * Nn + r];
        if (node < 0) node = 0;
        if (node >= NNODE) node = NNODE - 1;
        const float4* src = (const float4*)(emb + (size_t)node * Hh) + half * 16;
        const float d = sd[r];
        float* zdst = sZ + r * SZ_STRIDE + half * 64;
        #pragma unroll
        for (int c4 = 0; c4 < 16; c4++) {
            float4 v = src[c4];
            v.x = to_tf32(d * v.x); v.y = to_tf32(d * v.y);
            v.z = to_tf32(d * v.z); v.w = to_tf32(d * v.w);
            *(float4*)(zdst + c4 * 4) = v;
        }
    }
    __syncthreads();

    float acc[4][4][4];

    auto zero_acc = [&]() {
        #pragma unroll
        for (int mt = 0; mt < 4; mt++)
            #pragma unroll
            for (int nt = 0; nt < 4; nt++)
                #pragma unroll
                for (int e = 0; e < 4; e++) acc[mt][nt][e] = 0.0f;
    };

    auto compute = [&](int kt, int s) {
        const float* bufA = sA + s * A_STAGE;
        #pragma unroll
        for (int ks = 0; ks < 4; ks++) {
            uint32_t af[4][4], bf[4][2];
            #pragma unroll
            for (int mt = 0; mt < 4; mt++) {
                float4 v = *(const float4*)(bufA +
                            (((wm * 4 + mt) * 4 + ks) * 32 + lane) * 4);
                af[mt][0] = __float_as_uint(v.x);
                af[mt][1] = __float_as_uint(v.y);
                af[mt][2] = __float_as_uint(v.z);
                af[mt][3] = __float_as_uint(v.w);
            }
            const int krow = kt * 32 + ks * 8 + tc;
            #pragma unroll
            for (int nt = 0; nt < 4; nt++) {
                const int cb = wn * 32 + nt * 8 + gr;
                bf[nt][0] = __float_as_uint(sZ[krow * SZ_STRIDE + cb]);
                bf[nt][1] = __float_as_uint(sZ[(krow + 4) * SZ_STRIDE + cb]);
            }
            #pragma unroll
            for (int mt = 0; mt < 4; mt++)
                #pragma unroll
                for (int nt = 0; nt < 4; nt++)
                    mma_tf32(acc[mt][nt], af[mt], bf[nt]);
        }
    };

    // Drain rule (2 stages): tile kt+1 is newest for kt<=6 -> wait 1;
    // at kt==7 nothing newer exists -> wait 0.
    auto run_round = [&]() {
        #pragma unroll
        for (int kt = 0; kt < 8; kt++) {
            if (kt < 7) cp_wait<1>();
            else        cp_wait<0>();
            __syncthreads();
            compute(kt, kt & 1);
            __syncthreads();
            if (kt + 2 < 8) issue_tile(kt + 2, kt & 1);
        }
    };

    // ---- round 0 ----
    zero_acc();
    run_round();

    // prefetch round-1 A tiles while epilogue runs (touch only sA/cp, not sZ)
    issue_tile(0, 0);
    issue_tile(1, 1);

    // epilogue 0: Z1 = rna(0.8 d^2 W0 + c Z0), in-place in sZ
    #pragma unroll
    for (int mt = 0; mt < 4; mt++) {
        #pragma unroll
        for (int rr = 0; rr < 2; rr++) {
            const int r = wm * 64 + mt * 16 + gr + rr * 8;
            const float ws = 0.8f * sd[r] * sd[r];
            const float cc = sc[r];
            #pragma unroll
            for (int nt = 0; nt < 4; nt++) {
                const int col = wn * 32 + nt * 8 + tc * 2;
                float* zp = sZ + r * SZ_STRIDE + col;
                float z0 = zp[0], z1 = zp[1];
                zp[0] = to_tf32(ws * acc[mt][nt][rr * 2 + 0] + cc * z0);
                zp[1] = to_tf32(ws * acc[mt][nt][rr * 2 + 1] + cc * z1);
            }
        }
    }
    __syncthreads();

    // ---- round 1 ----
    zero_acc();
    run_round();

    // epilogue 1: out = 0.8 d W1 + (c/d) Z1
    float* __restrict__ dst = out + (size_t)b * Nn * Hh;
    #pragma unroll
    for (int mt = 0; mt < 4; mt++) {
        #pragma unroll
        for (int rr = 0; rr < 2; rr++) {
            const int r = wm * 64 + mt * 16 + gr + rr * 8;
            const float d  = sd[r];
            const float ws = 0.8f * d;
            const float zs = sc[r] / d;
            #pragma unroll
            for (int nt = 0; nt < 4; nt++) {
                const int col = wn * 32 + nt * 8 + tc * 2;
                const float* zp = sZ + r * SZ_STRIDE + col;
                float o0 = ws * acc[mt][nt][rr * 2 + 0] + zs * zp[0];
                float o1 = ws * acc[mt][nt][rr * 2 + 1] + zs * zp[1];
                *(float2*)(dst + (size_t)r * Hh + col) = make_float2(o0, o1);
            }
        }
    }
}

// ---------------------------------------------------------------------------
extern "C" void kernel_launch(void* const* d_in, const int* in_sizes, int n_in,
                              void* d_out, int out_size) {
    const void*  inputs = nullptr;
    const float* A      = nullptr;
    const float* emb    = nullptr;

    for (int i = 0; i < n_in; ++i) {
        if (in_sizes[i] == Bsz * Nn)               inputs = d_in[i];
        else if (in_sizes[i] == Bsz * Nn * 2 * Nn) A      = (const float*)d_in[i];
        else if (in_sizes[i] == NNODE * Hh)        emb    = (const float*)d_in[i];
    }
    if (!inputs) inputs = d_in[0];
    if (!A)      A      = (const float*)d_in[1];
    if (!emb)    emb    = (const float*)d_in[2];

    float* out = (float*)d_out;

    static bool attr_set = false;
    const int smem_bytes = SMEM_FLOATS * sizeof(float);   // 202,752 B
    if (!attr_set) {
        cudaFuncSetAttribute(sgc_fused, cudaFuncAttributeMaxDynamicSharedMemorySize,
                             smem_bytes);
        attr_set = true;
    }

    detect_kernel<<<1, 1>>>((const unsigned long long*)inputs);
    prep_kernel<<<dim3(16, Bsz), 256>>>(A);
    sgc_fused<<<Bsz, 512, smem_bytes>>>(inputs, emb, out);
}

// round 9
// speedup vs baseline: 1.3080x; 1.0729x over previous
#include <cuda_runtime.h>
#include <cstdint>

// ---------------------------------------------------------------------------
// B=512, N=256, H=128
//   A2 = A[:,:,:256] + A[:,:,256:],  d_i = rsqrt(rowsum(A2)+1)
//   A_mix = 0.8*D*A2*D + diag(c),    c_i = 0.1 + d_i^2*(0.7 - 0.1*A2_ii)
//   out = A_mix @ (A_mix @ emb[idx])
// Z-space: Z0 = D*emb[idx]; Z1 = 0.8 d^2 (A2@Z0) + c.*Z0;
//          out = 0.8 d (A2@Z1) + (c/d).*Z1
//
// Engine: legacy mma.sync m16n8k8 tf32 (tcgen05 blocked: harness targets
// sm_103 without the 'a' feature set).
// Fused kernel: grid (2 h-halves, 512 batches), 256 thr, 2 CTAs/SM.
//   A2: fragment-permuted tf32 image, streamed in k16 chunks (2-stage cp.async)
//     per batch: [kc 16][mblk 16][ksg 2][lane 32] float4
//     lane (gr,tc) float4 = A2[mblk*16+gr(+8)][kc*16+ksg*8+tc(+4)] (frag order)
//   Z: smem-resident pair-interleaved image (per h-half, 64 cols):
//     pair slot (k8,t) holds (Z[k8*8+t][h], Z[k8*8+t+4][h]) -> B frag = 1 LDS.64
// ---------------------------------------------------------------------------

#define Bsz 512
#define Nn  256
#define Hh  128
#define NNODE 50000

__device__ float g_A2p[(size_t)Bsz * Nn * Nn];   // fragment-permuted tf32
__device__ float g_d  [(size_t)Bsz * Nn];
__device__ float g_c  [(size_t)Bsz * Nn];

__device__ __forceinline__ float to_tf32(float x) {
    uint32_t u;
    asm("cvt.rna.tf32.f32 %0, %1;" : "=r"(u) : "f"(x));
    return __uint_as_float(u);
}

// ---------------------------------------------------------------------------
// prep: 16-row slab per block. d, c, and chunk-major fragment-permuted tf32
// A2 image. grid (16, 512), block 256.
// ---------------------------------------------------------------------------
__global__ __launch_bounds__(256)
void prep_kernel(const float* __restrict__ A) {
    __shared__ float s2[16 * 260];
    const int b    = blockIdx.y;
    const int mblk = blockIdx.x;
    const int t    = threadIdx.x;
    const int i0   = mblk * 16;

    #pragma unroll
    for (int p = 0; p < 4; p++) {
        int fidx = t + p * 256;
        int row  = fidx >> 6;
        int c4   = fidx & 63;
        const float4* src =
            (const float4*)(A + ((size_t)(b * Nn + i0 + row)) * (2 * Nn));
        float4 a  = src[c4];
        float4 bb = src[c4 + 64];
        *(float4*)(s2 + row * 260 + c4 * 4) =
            make_float4(a.x + bb.x, a.y + bb.y, a.z + bb.z, a.w + bb.w);
    }
    __syncthreads();

    const int lane = t & 31, w = t >> 5;
    #pragma unroll
    for (int rr = 0; rr < 2; rr++) {
        int row = w * 2 + rr;
        float s = 0.0f;
        #pragma unroll
        for (int k = 0; k < 8; k++) s += s2[row * 260 + lane + 32 * k];
        #pragma unroll
        for (int o = 16; o; o >>= 1) s += __shfl_xor_sync(0xFFFFFFFFu, s, o);
        if (lane == 0) {
            int i = i0 + row;
            float aii = s2[row * 260 + i];
            float d = rsqrtf(s + 1.0f);
            g_d[b * Nn + i] = d;
            g_c[b * Nn + i] = 0.1f + d * d * (0.7f - 0.1f * aii);
        }
    }

    // fragment-permuted, chunk-major write
    float4* dst = (float4*)g_A2p + (size_t)b * 16384;
    #pragma unroll
    for (int p = 0; p < 4; p++) {
        int q    = t + p * 256;          // 0..1023 = ksgg*32 + lp
        int ksgg = q >> 5;               // global k8 index 0..31
        int lp   = q & 31;
        int gr2  = lp >> 2, tc2 = lp & 3;
        int col  = ksgg * 8;
        float e0 = s2[(gr2    ) * 260 + col + tc2    ];
        float e1 = s2[(gr2 + 8) * 260 + col + tc2    ];
        float e2 = s2[(gr2    ) * 260 + col + tc2 + 4];
        float e3 = s2[(gr2 + 8) * 260 + col + tc2 + 4];
        int kc  = ksgg >> 1;
        int ksg = ksgg & 1;
        dst[kc * 1024 + mblk * 64 + ksg * 32 + lp] =
            make_float4(to_tf32(e0), to_tf32(e1), to_tf32(e2), to_tf32(e3));
    }
}

// ---------------------------------------------------------------------------
// MMA / cp.async helpers
// ---------------------------------------------------------------------------
__device__ __forceinline__ void mma_tf32(float* c, const uint32_t* a, const uint32_t* b) {
    asm volatile(
        "mma.sync.aligned.m16n8k8.row.col.f32.tf32.tf32.f32 "
        "{%0,%1,%2,%3}, {%4,%5,%6,%7}, {%8,%9}, {%0,%1,%2,%3};\n"
        : "+f"(c[0]), "+f"(c[1]), "+f"(c[2]), "+f"(c[3])
        : "r"(a[0]), "r"(a[1]), "r"(a[2]), "r"(a[3]),
          "r"(b[0]), "r"(b[1]));
}

__device__ __forceinline__ void cp_async16(uint32_t smem_addr, const void* gptr) {
    asm volatile("cp.async.cg.shared.global [%0], [%1], 16;\n"
                 :: "r"(smem_addr), "l"(gptr));
}
__device__ __forceinline__ void cp_commit() {
    asm volatile("cp.async.commit_group;\n");
}
template <int N>
__device__ __forceinline__ void cp_wait() {
    asm volatile("cp.async.wait_group %0;\n" :: "n"(N) : "memory");
}

// ---------------------------------------------------------------------------
// Fused kernel. grid (2, 512), block 256 (8 warps: 4m x 2n, warp tile 64x32).
// smem: Z pairs 68.0KB | A 2x16KB | d 1KB | c 1KB  ~= 104.5KB -> 2 CTAs/SM.
// ---------------------------------------------------------------------------
#define ZP_STRIDE 68                     // pair-units per tc-row (mod 16 == 4)
#define SZ_FLOATS (128 * ZP_STRIDE * 2)  // 17408 floats
#define SA_CHUNK  4096                   // floats per stage (k16 chunk)
#define SMEM_FLOATS (SZ_FLOATS + 2 * SA_CHUNK + 2 * 256)

__global__ __launch_bounds__(256, 2)
void sgc_fused(const void* __restrict__ idx_raw,
               const float* __restrict__ emb,
               float* __restrict__ out) {
    extern __shared__ float smem[];
    float* sZ = smem;
    float* sA = smem + SZ_FLOATS;
    float* sd = sA + 2 * SA_CHUNK;
    float* sc = sd + 256;

    const int half = blockIdx.x;    // h-half 0/1
    const int b    = blockIdx.y;
    const int tid  = threadIdx.x;
    const int lane = tid & 31;
    const int w    = tid >> 5;
    const int wm   = w & 3;         // 4 m-blocks of 64
    const int wn   = w >> 2;        // 2 n-blocks of 32
    const int gr   = lane >> 2;
    const int tc   = lane & 3;

    // index dtype detection (true int64 indices < 50000 -> high words zero)
    const unsigned long long* iq = (const unsigned long long*)idx_raw;
    int is64 = 1;
    #pragma unroll
    for (int i = 0; i < 16; i++)
        if (iq[i] >> 32) is64 = 0;

    sd[tid] = g_d[b * Nn + tid];
    sc[tid] = g_c[b * Nn + tid];

    const float4* __restrict__ A2f4 = (const float4*)g_A2p + (size_t)b * 16384;
    const uint32_t sA_u32 = (uint32_t)__cvta_generic_to_shared(sA);

    auto issue_chunk = [&](int kc, int s) {
        const float4* src = A2f4 + kc * 1024;
        uint32_t dst = sA_u32 + s * (SA_CHUNK * 4);
        #pragma unroll
        for (int i = 0; i < 4; i++) {
            int q = tid + i * 256;
            cp_async16(dst + q * 16, src + q);
        }
        cp_commit();
    };

    issue_chunk(0, 0);
    issue_chunk(1, 1);
    __syncthreads();   // sd visible

    // Z0 gather: thread <-> k row; this half's 64 emb columns
    {
        const int k = tid;
        long long node = is64 ? ((const long long*)idx_raw)[b * Nn + k]
                              : (long long)((const int*)idx_raw)[b * Nn + k];
        if (node < 0) node = 0;
        if (node >= NNODE) node = NNODE - 1;
        const float dk = sd[k];
        const int slot = (k >> 3) * 4 + (k & 3);
        const int comp = (k >> 2) & 1;
        float* zrow = sZ + slot * (ZP_STRIDE * 2) + comp;
        const float4* src = (const float4*)(emb + (size_t)node * Hh + half * 64);
        #pragma unroll
        for (int j = 0; j < 16; j++) {
            float4 v = src[j];
            const int h = j * 4;
            zrow[(h    ) * 2] = to_tf32(dk * v.x);
            zrow[(h + 1) * 2] = to_tf32(dk * v.y);
            zrow[(h + 2) * 2] = to_tf32(dk * v.z);
            zrow[(h + 3) * 2] = to_tf32(dk * v.w);
        }
    }
    __syncthreads();

    float acc[4][4][4];
    auto zero_acc = [&]() {
        #pragma unroll
        for (int mt = 0; mt < 4; mt++)
            #pragma unroll
            for (int nt = 0; nt < 4; nt++)
                #pragma unroll
                for (int e = 0; e < 4; e++) acc[mt][nt][e] = 0.0f;
    };

    auto compute = [&](int kc, int s) {
        const float* bufA = sA + s * SA_CHUNK;
        #pragma unroll
        for (int ks = 0; ks < 2; ks++) {
            const int k8 = kc * 2 + ks;      // global k8 index
            uint32_t af[4][4], bf[4][2];
            #pragma unroll
            for (int mt = 0; mt < 4; mt++) {
                float4 v = *(const float4*)(bufA +
                            (((wm * 4 + mt) * 2 + ks) * 32 + lane) * 4);
                af[mt][0] = __float_as_uint(v.x);
                af[mt][1] = __float_as_uint(v.y);
                af[mt][2] = __float_as_uint(v.z);
                af[mt][3] = __float_as_uint(v.w);
            }
            #pragma unroll
            for (int nt = 0; nt < 4; nt++) {
                const int cb = wn * 32 + nt * 8 + gr;
                float2 bv = *(const float2*)(sZ +
                            ((k8 * 4 + tc) * ZP_STRIDE + cb) * 2);
                bf[nt][0] = __float_as_uint(bv.x);
                bf[nt][1] = __float_as_uint(bv.y);
            }
            #pragma unroll
            for (int mt = 0; mt < 4; mt++)
                #pragma unroll
                for (int nt = 0; nt < 4; nt++)
                    mma_tf32(acc[mt][nt], af[mt], bf[nt]);
        }
    };

    // Drain: while chunks still issue (kc<15) chunk kc is second-newest.
    auto run_round = [&]() {
        #pragma unroll 1
        for (int kc = 0; kc < 16; kc++) {
            if (kc < 15) cp_wait<1>();
            else         cp_wait<0>();
            __syncthreads();
            compute(kc, kc & 1);
            __syncthreads();
            if (kc + 2 < 16) issue_chunk(kc + 2, kc & 1);
        }
    };

    // ================= round 0 =================
    zero_acc();
    run_round();

    // prefetch round-1 chunks (stages free; touches only sA)
    issue_chunk(0, 0);
    issue_chunk(1, 1);

    // epilogue 0: Z1 = tf32(0.8 d^2 W0 + c Z0), in place
    #pragma unroll
    for (int mt = 0; mt < 4; mt++) {
        #pragma unroll
        for (int rr = 0; rr < 2; rr++) {
            const int r = wm * 64 + mt * 16 + gr + rr * 8;
            const float ws = 0.8f * sd[r] * sd[r];
            const float cc = sc[r];
            float* base = sZ + ((r >> 3) * 4 + (r & 3)) * (ZP_STRIDE * 2)
                             + ((r >> 2) & 1);
            #pragma unroll
            for (int nt = 0; nt < 4; nt++) {
                const int col = wn * 32 + nt * 8 + tc * 2;
                float z0 = base[(col    ) * 2];
                float z1 = base[(col + 1) * 2];
                base[(col    ) * 2] = to_tf32(ws * acc[mt][nt][rr * 2 + 0] + cc * z0);
                base[(col + 1) * 2] = to_tf32(ws * acc[mt][nt][rr * 2 + 1] + cc * z1);
            }
        }
    }
    __syncthreads();

    // ================= round 1 =================
    zero_acc();
    run_round();

    // epilogue 1: out = 0.8 d W1 + (c/d) Z1
    float* __restrict__ dstb = out + (size_t)b * Nn * Hh + half * 64;
    #pragma unroll
    for (int mt = 0; mt < 4; mt++) {
        #pragma unroll
        for (int rr = 0; rr < 2; rr++) {
            const int r = wm * 64 + mt * 16 + gr + rr * 8;
            const float dk = sd[r];
            const float ws = 0.8f * dk;
            const float zs = sc[r] / dk;
            const float* base = sZ + ((r >> 3) * 4 + (r & 3)) * (ZP_STRIDE * 2)
                                   + ((r >> 2) & 1);
            #pragma unroll
            for (int nt = 0; nt < 4; nt++) {
                const int col = wn * 32 + nt * 8 + tc * 2;
                float o0 = ws * acc[mt][nt][rr * 2 + 0] + zs * base[(col    ) * 2];
                float o1 = ws * acc[mt][nt][rr * 2 + 1] + zs * base[(col + 1) * 2];
                *(float2*)(dstb + (size_t)r * Hh + col) = make_float2(o0, o1);
            }
        }
    }
}

// ---------------------------------------------------------------------------
extern "C" void kernel_launch(void* const* d_in, const int* in_sizes, int n_in,
                              void* d_out, int out_size) {
    const void*  inputs = nullptr;
    const float* A      = nullptr;
    const float* emb    = nullptr;

    for (int i = 0; i < n_in; ++i) {
        if (in_sizes[i] == Bsz * Nn)               inputs = d_in[i];
        else if (in_sizes[i] == Bsz * Nn * 2 * Nn) A      = (const float*)d_in[i];
        else if (in_sizes[i] == NNODE * Hh)        emb    = (const float*)d_in[i];
    }
    if (!inputs) inputs = d_in[0];
    if (!A)      A      = (const float*)d_in[1];
    if (!emb)    emb    = (const float*)d_in[2];

    float* out = (float*)d_out;

    static bool attr_set = false;
    const int smem_bytes = SMEM_FLOATS * sizeof(float);   // 104,960 B
    if (!attr_set) {
        cudaFuncSetAttribute(sgc_fused, cudaFuncAttributeMaxDynamicSharedMemorySize,
                             smem_bytes);
        attr_set = true;
    }

    prep_kernel<<<dim3(16, Bsz), 256>>>(A);
    sgc_fused<<<dim3(2, Bsz), 256, smem_bytes>>>(inputs, emb, out);
}

// round 10
// speedup vs baseline: 1.4349x; 1.0970x over previous
#include <cuda_runtime.h>
#include <cstdint>

// ---------------------------------------------------------------------------
// B=512, N=256, H=128
//   A2 = A[:,:,:256] + A[:,:,256:],  d_i = rsqrt(rowsum(A2)+1)
//   A_mix = 0.8*D*A2*D + diag(c),    c_i = 0.1 + d_i^2*(0.7 - 0.1*A2_ii)
//   out = A_mix @ (A_mix @ emb[idx])
// Z-space: Z0 = D*emb[idx]; Z1 = 0.8 d^2 (A2@Z0) + c.*Z0;
//          out = 0.8 d (A2@Z1) + (c/d).*Z1
//
// Engine: legacy mma.sync m16n8k8 tf32. Fused kernel with FREE-RUNNING warps:
// no smem staging of A — fragment-permuted A2 is read straight from global
// (L2-resident: 148 batches x 256KB = 38MB), one-k8-ahead register prefetch.
// Mainloop has no barriers at all; warps sync only at round boundaries.
//   A2p per batch: [k8 32][mblk 16][lane 32] float4
//     lane(gr,tc) float4 = A2[mblk*16+gr(+8)][k8*8+tc(+4)]  (frag order)
//   Z: smem pair-interleaved (per h-half): slot(k8,t) = (Z[k8*8+t], Z[k8*8+t+4])
// ---------------------------------------------------------------------------

#define Bsz 512
#define Nn  256
#define Hh  128
#define NNODE 50000

__device__ float g_A2p[(size_t)Bsz * Nn * Nn];   // fragment-permuted tf32
__device__ float g_d  [(size_t)Bsz * Nn];
__device__ float g_c  [(size_t)Bsz * Nn];

__device__ __forceinline__ float to_tf32(float x) {
    uint32_t u;
    asm("cvt.rna.tf32.f32 %0, %1;" : "=r"(u) : "f"(x));
    return __uint_as_float(u);
}

// ---------------------------------------------------------------------------
// prep: 16-row slab per block. d, c, fragment-permuted tf32 A2 image
// (k8-major). grid (16, 512), block 256.
// ---------------------------------------------------------------------------
__global__ __launch_bounds__(256)
void prep_kernel(const float* __restrict__ A) {
    __shared__ float s2[16 * 260];
    const int b    = blockIdx.y;
    const int mblk = blockIdx.x;
    const int t    = threadIdx.x;
    const int i0   = mblk * 16;

    #pragma unroll
    for (int p = 0; p < 4; p++) {
        int fidx = t + p * 256;
        int row  = fidx >> 6;
        int c4   = fidx & 63;
        const float4* src =
            (const float4*)(A + ((size_t)(b * Nn + i0 + row)) * (2 * Nn));
        float4 a  = src[c4];
        float4 bb = src[c4 + 64];
        *(float4*)(s2 + row * 260 + c4 * 4) =
            make_float4(a.x + bb.x, a.y + bb.y, a.z + bb.z, a.w + bb.w);
    }
    __syncthreads();

    const int lane = t & 31, w = t >> 5;
    #pragma unroll
    for (int rr = 0; rr < 2; rr++) {
        int row = w * 2 + rr;
        float s = 0.0f;
        #pragma unroll
        for (int k = 0; k < 8; k++) s += s2[row * 260 + lane + 32 * k];
        #pragma unroll
        for (int o = 16; o; o >>= 1) s += __shfl_xor_sync(0xFFFFFFFFu, s, o);
        if (lane == 0) {
            int i = i0 + row;
            float aii = s2[row * 260 + i];
            float d = rsqrtf(s + 1.0f);
            g_d[b * Nn + i] = d;
            g_c[b * Nn + i] = 0.1f + d * d * (0.7f - 0.1f * aii);
        }
    }

    // fragment-permuted, k8-major write: dst[k8*512 + mblk*32 + lane]
    float4* dst = (float4*)g_A2p + (size_t)b * 16384;
    #pragma unroll
    for (int p = 0; p < 4; p++) {
        int q    = t + p * 256;          // 0..1023 = k8*32 + lp
        int k8   = q >> 5;
        int lp   = q & 31;
        int gr2  = lp >> 2, tc2 = lp & 3;
        int col  = k8 * 8;
        float e0 = s2[(gr2    ) * 260 + col + tc2    ];
        float e1 = s2[(gr2 + 8) * 260 + col + tc2    ];
        float e2 = s2[(gr2    ) * 260 + col + tc2 + 4];
        float e3 = s2[(gr2 + 8) * 260 + col + tc2 + 4];
        dst[k8 * 512 + mblk * 32 + lp] =
            make_float4(to_tf32(e0), to_tf32(e1), to_tf32(e2), to_tf32(e3));
    }
}

// ---------------------------------------------------------------------------
__device__ __forceinline__ void mma_tf32(float* c, const uint32_t* a, const uint32_t* b) {
    asm volatile(
        "mma.sync.aligned.m16n8k8.row.col.f32.tf32.tf32.f32 "
        "{%0,%1,%2,%3}, {%4,%5,%6,%7}, {%8,%9}, {%0,%1,%2,%3};\n"
        : "+f"(c[0]), "+f"(c[1]), "+f"(c[2]), "+f"(c[3])
        : "r"(a[0]), "r"(a[1]), "r"(a[2]), "r"(a[3]),
          "r"(b[0]), "r"(b[1]));
}

// ---------------------------------------------------------------------------
// Fused kernel. grid (2 h-halves, 512 batches), 256 thr (8 warps: 4m x 2n,
// warp tile 64x32). smem: Z pairs 68KB + d/c 2KB -> 2 CTAs/SM, 16 warps/SM.
// ---------------------------------------------------------------------------
#define ZP_STRIDE 68                     // pair-units per tc-row (mod 16 == 4)
#define SZ_FLOATS (128 * ZP_STRIDE * 2)  // 17408 floats
#define SMEM_FLOATS (SZ_FLOATS + 2 * 256)

__global__ __launch_bounds__(256, 2)
void sgc_fused(const void* __restrict__ idx_raw,
               const float* __restrict__ emb,
               float* __restrict__ out) {
    extern __shared__ float smem[];
    float* sZ = smem;
    float* sd = smem + SZ_FLOATS;
    float* sc = sd + 256;

    const int half = blockIdx.x;
    const int b    = blockIdx.y;
    const int tid  = threadIdx.x;
    const int lane = tid & 31;
    const int w    = tid >> 5;
    const int wm   = w & 3;
    const int wn   = w >> 2;
    const int gr   = lane >> 2;
    const int tc   = lane & 3;

    // index dtype detection (true int64 indices < 50000 -> high words zero)
    const unsigned long long* iq = (const unsigned long long*)idx_raw;
    int is64 = 1;
    #pragma unroll
    for (int i = 0; i < 16; i++)
        if (iq[i] >> 32) is64 = 0;

    sd[tid] = g_d[b * Nn + tid];
    sc[tid] = g_c[b * Nn + tid];
    __syncthreads();

    // Z0 gather: thread <-> k row; this half's 64 emb columns
    {
        const int k = tid;
        long long node = is64 ? ((const long long*)idx_raw)[b * Nn + k]
                              : (long long)((const int*)idx_raw)[b * Nn + k];
        if (node < 0) node = 0;
        if (node >= NNODE) node = NNODE - 1;
        const float dk = sd[k];
        const int slot = (k >> 3) * 4 + (k & 3);
        const int comp = (k >> 2) & 1;
        float* zrow = sZ + slot * (ZP_STRIDE * 2) + comp;
        const float4* src = (const float4*)(emb + (size_t)node * Hh + half * 64);
        #pragma unroll
        for (int j = 0; j < 16; j++) {
            float4 v = src[j];
            const int h = j * 4;
            zrow[(h    ) * 2] = to_tf32(dk * v.x);
            zrow[(h + 1) * 2] = to_tf32(dk * v.y);
            zrow[(h + 2) * 2] = to_tf32(dk * v.z);
            zrow[(h + 3) * 2] = to_tf32(dk * v.w);
        }
    }
    __syncthreads();

    const float4* __restrict__ A2f4 =
        (const float4*)g_A2p + (size_t)b * 16384 + (wm * 4) * 32 + lane;

    float acc[4][4][4];
    auto zero_acc = [&]() {
        #pragma unroll
        for (int mt = 0; mt < 4; mt++)
            #pragma unroll
            for (int nt = 0; nt < 4; nt++)
                #pragma unroll
                for (int e = 0; e < 4; e++) acc[mt][nt][e] = 0.0f;
    };

    // free-running mainloop: NO barriers. A frags LDG'd from L2 with
    // one-k8-ahead register prefetch; B frags LDS.64 from resident sZ.
    auto run_round = [&]() {
        float4 abuf[2][4];
        #pragma unroll
        for (int mt = 0; mt < 4; mt++)
            abuf[0][mt] = __ldg(A2f4 + mt * 32);

        #pragma unroll 2
        for (int k8 = 0; k8 < 32; k8++) {
            const int cur = k8 & 1;
            if (k8 < 31) {
                const float4* nsrc = A2f4 + (k8 + 1) * 512;
                #pragma unroll
                for (int mt = 0; mt < 4; mt++)
                    abuf[cur ^ 1][mt] = __ldg(nsrc + mt * 32);
            }
            uint32_t bf[4][2];
            #pragma unroll
            for (int nt = 0; nt < 4; nt++) {
                const int cb = wn * 32 + nt * 8 + gr;
                float2 bv = *(const float2*)(sZ +
                            ((k8 * 4 + tc) * ZP_STRIDE + cb) * 2);
                bf[nt][0] = __float_as_uint(bv.x);
                bf[nt][1] = __float_as_uint(bv.y);
            }
            #pragma unroll
            for (int mt = 0; mt < 4; mt++) {
                uint32_t af[4];
                af[0] = __float_as_uint(abuf[cur][mt].x);
                af[1] = __float_as_uint(abuf[cur][mt].y);
                af[2] = __float_as_uint(abuf[cur][mt].z);
                af[3] = __float_as_uint(abuf[cur][mt].w);
                #pragma unroll
                for (int nt = 0; nt < 4; nt++)
                    mma_tf32(acc[mt][nt], af, bf[nt]);
            }
        }
    };

    // ================= round 0 =================
    zero_acc();
    run_round();

    __syncthreads();   // all warps done READING sZ before it is rewritten

    // epilogue 0: Z1 = tf32(0.8 d^2 W0 + c Z0), in place
    #pragma unroll
    for (int mt = 0; mt < 4; mt++) {
        #pragma unroll
        for (int rr = 0; rr < 2; rr++) {
            const int r = wm * 64 + mt * 16 + gr + rr * 8;
            const float ws = 0.8f * sd[r] * sd[r];
            const float cc = sc[r];
            float* base = sZ + ((r >> 3) * 4 + (r & 3)) * (ZP_STRIDE * 2)
                             + ((r >> 2) & 1);
            #pragma unroll
            for (int nt = 0; nt < 4; nt++) {
                const int col = wn * 32 + nt * 8 + tc * 2;
                float z0 = base[(col    ) * 2];
                float z1 = base[(col + 1) * 2];
                base[(col    ) * 2] = to_tf32(ws * acc[mt][nt][rr * 2 + 0] + cc * z0);
                base[(col + 1) * 2] = to_tf32(ws * acc[mt][nt][rr * 2 + 1] + cc * z1);
            }
        }
    }
    __syncthreads();

    // ================= round 1 =================
    zero_acc();
    run_round();

    // epilogue 1: out = 0.8 d W1 + (c/d) Z1   (sZ read-only here; no sync)
    float* __restrict__ dstb = out + (size_t)b * Nn * Hh + half * 64;
    #pragma unroll
    for (int mt = 0; mt < 4; mt++) {
        #pragma unroll
        for (int rr = 0; rr < 2; rr++) {
            const int r = wm * 64 + mt * 16 + gr + rr * 8;
            const float dk = sd[r];
            const float ws = 0.8f * dk;
            const float zs = sc[r] / dk;
            const float* base = sZ + ((r >> 3) * 4 + (r & 3)) * (ZP_STRIDE * 2)
                                   + ((r >> 2) & 1);
            #pragma unroll
            for (int nt = 0; nt < 4; nt++) {
                const int col = wn * 32 + nt * 8 + tc * 2;
                float o0 = ws * acc[mt][nt][rr * 2 + 0] + zs * base[(col    ) * 2];
                float o1 = ws * acc[mt][nt][rr * 2 + 1] + zs * base[(col + 1) * 2];
                *(float2*)(dstb + (size_t)r * Hh + col) = make_float2(o0, o1);
            }
        }
    }
}

// ---------------------------------------------------------------------------
extern "C" void kernel_launch(void* const* d_in, const int* in_sizes, int n_in,
                              void* d_out, int out_size) {
    const void*  inputs = nullptr;
    const float* A      = nullptr;
    const float* emb    = nullptr;

    for (int i = 0; i < n_in; ++i) {
        if (in_sizes[i] == Bsz * Nn)               inputs = d_in[i];
        else if (in_sizes[i] == Bsz * Nn * 2 * Nn) A      = (const float*)d_in[i];
        else if (in_sizes[i] == NNODE * Hh)        emb    = (const float*)d_in[i];
    }
    if (!inputs) inputs = d_in[0];
    if (!A)      A      = (const float*)d_in[1];
    if (!emb)    emb    = (const float*)d_in[2];

    float* out = (float*)d_out;

    static bool attr_set = false;
    const int smem_bytes = SMEM_FLOATS * sizeof(float);   // 71,680 B
    if (!attr_set) {
        cudaFuncSetAttribute(sgc_fused, cudaFuncAttributeMaxDynamicSharedMemorySize,
                             smem_bytes);
        attr_set = true;
    }

    prep_kernel<<<dim3(16, Bsz), 256>>>(A);
    sgc_fused<<<dim3(2, Bsz), 256, smem_bytes>>>(inputs, emb, out);
}